// round 7
// baseline (speedup 1.0000x reference)
#include <cuda_runtime.h>
#include <cuda_bf16.h>
#include <cuda_fp16.h>
#include <cstdint>

// ============================================================================
// HQQ grouped int4 GEMM, sm_103 base target, mma.sync fp16 path.
//
// W = q*s + zp (zp = z - 8s).  Per quant group g (K-chunk of 64):
//   P_g     = x_f16 @ q_f16     (q exact in fp16; x rounded, rel ~2^-11)
//   mast   += P_g * s[g, n]     (fp32 FFMA, s exact)
//   out    += R @ Z^T           (rank-32 zero-point correction, bf16 hi/lo)
//
// Pipeline: per iteration, the NEXT chunk's STS pieces and the chunk-after's
// LDG are interleaved with the CURRENT chunk's ldsm+MMA, one barrier/chunk.
// ============================================================================

namespace {

constexpr int kE   = 8;
constexpr int kIN  = 2048;
constexpr int kOUT = 2048;
constexpr int kG   = 32;

constexpr int kBM  = 128;
constexpr int kBN  = 128;
constexpr int kBK  = 64;                  // == group size
constexpr int kNCh = kIN / kBK;           // 32
constexpr int kThreads = 512;             // 16 warps, 4x4 warp grid

constexpr int kTileB  = kBM * kBK * 2;    // 16 KB fp16 tile
constexpr int kStageB = 2 * kTileB + 1024;           // A | B | s floats
constexpr int kRZoff  = 2 * kStageB;                 // R_hi R_lo Z_hi Z_lo, 8KB each
constexpr int kSmemB  = kRZoff + 4 * 8192;           // 100352

// ---------------------------------------------------------------------------

__device__ __forceinline__ uint32_t smem_u32(const void* p) {
  uint32_t a;
  asm("{ .reg .u64 t; cvta.to.shared.u64 t, %1; cvt.u32.u64 %0, t; }" : "=r"(a) : "l"(p));
  return a;
}

__device__ __forceinline__ uint32_t pack_f16x2(float lo, float hi) {
  uint32_t r;
  asm("cvt.rn.f16x2.f32 %0, %1, %2;" : "=r"(r) : "f"(hi), "f"(lo));
  return r;
}

__device__ __forceinline__ uint32_t sw128(uint32_t off) {
  return off ^ ((off >> 3) & 0x70);
}

__device__ __forceinline__ void ldsm_x4(uint32_t* r, uint32_t addr) {
  asm volatile("ldmatrix.sync.aligned.m8n8.x4.shared.b16 {%0,%1,%2,%3}, [%4];"
               : "=r"(r[0]), "=r"(r[1]), "=r"(r[2]), "=r"(r[3]) : "r"(addr));
}

__device__ __forceinline__ void ldsm_x2(uint32_t* r, uint32_t addr) {
  asm volatile("ldmatrix.sync.aligned.m8n8.x2.shared.b16 {%0,%1}, [%2];"
               : "=r"(r[0]), "=r"(r[1]) : "r"(addr));
}

__device__ __forceinline__ void mma_f16(float* c, const uint32_t* a,
                                        uint32_t b0, uint32_t b1) {
  asm volatile(
      "mma.sync.aligned.m16n8k16.row.col.f32.f16.f16.f32 "
      "{%0,%1,%2,%3}, {%4,%5,%6,%7}, {%8,%9}, {%0,%1,%2,%3};"
      : "+f"(c[0]), "+f"(c[1]), "+f"(c[2]), "+f"(c[3])
      : "r"(a[0]), "r"(a[1]), "r"(a[2]), "r"(a[3]), "r"(b0), "r"(b1));
}

__device__ __forceinline__ void mma_bf16(float* c, const uint32_t* a, const uint32_t* b) {
  asm volatile(
      "mma.sync.aligned.m16n8k16.row.col.f32.bf16.bf16.f32 "
      "{%0,%1,%2,%3}, {%4,%5,%6,%7}, {%8,%9}, {%0,%1,%2,%3};"
      : "+f"(c[0]), "+f"(c[1]), "+f"(c[2]), "+f"(c[3])
      : "r"(a[0]), "r"(a[1]), "r"(a[2]), "r"(a[3]), "r"(b[0]), "r"(b[1]));
}

// ---------------------------------------------------------------------------

__global__ void __launch_bounds__(kThreads)
hqq_mma_kernel(const float* __restrict__ x,
               const int* __restrict__ qw,
               const float* __restrict__ snz,
               const int* __restrict__ tpe,
               float* __restrict__ out) {
  extern __shared__ __align__(1024) char smem[];
  const int tid = threadIdx.x;
  const int wid = tid >> 5;
  const int l   = tid & 31;

  const int e  = blockIdx.z;
  const int nt = blockIdx.x;
  const int mt = blockIdx.y;

  int off = 0, cnt = 0;
#pragma unroll
  for (int i = 0; i < kE; i++) {
    int c = __ldg(&tpe[i]);
    if (i < e) off += c;
    if (i == e) cnt = c;
  }
  if (mt * kBM >= cnt) return;

  const int row0  = off + mt * kBM;
  const int nrows = min(kBM, cnt - mt * kBM);
  const int n0    = nt * kBN;

  const uint32_t sbase = smem_u32(smem);

  // ---- fill mappings ----
  const int a_c4 = l & 15;
  const int a_mr = tid >> 4;
  const int b_n0  = 2 * ((wid & 7) * 8 + (l >> 2));
  const int b_kpb = (wid >> 3) * 16 + (l & 3);

  // ---- mma fragment addressing ----
  const int wm = wid >> 2;
  const int wn = wid & 3;
  const int rowA0 = wm * 32 + (l & 15);
  const int segA  = l >> 4;
  const int rowBx4 = wn * 32 + ((l >> 4) & 1) * 8 + (l & 7);
  const int segBx4 = (l >> 3) & 1;
  const int rowB0 = wn * 32 + (l & 7);
  const int segB  = (l >> 3) & 1;

  // ---- staging ----
  float4 xv[4];
  int2   qva[4], qvb[4];
  float2 szv = make_float2(0.f, 0.f);

  float mast[32];
#pragma unroll
  for (int i = 0; i < 32; i++) mast[i] = 0.f;

  auto load_chunk = [&](int ch) {
    const int k0 = ch * kBK;
    const float* xp = x + ((size_t)(row0 + a_mr)) * kIN + k0 + a_c4 * 4;
#pragma unroll
    for (int p = 0; p < 4; p++) {
      const int m = a_mr + p * 32;
      xv[p] = (m < nrows) ? *(const float4*)(xp + (size_t)p * 32 * kIN)
                          : make_float4(0.f, 0.f, 0.f, 0.f);
    }
    const int* qb = qw + ((size_t)e * kIN + k0) * kOUT + n0 + b_n0;
#pragma unroll
    for (int p = 0; p < 4; p++) {
      const int kk = 2 * (b_kpb + 4 * p);
      qva[p] = *(const int2*)(qb + (size_t)kk * kOUT);
      qvb[p] = *(const int2*)(qb + (size_t)(kk + 1) * kOUT);
    }
    if (tid < 128)
      szv = *(const float2*)(snz + (((size_t)e * kG + ch) * kOUT + n0 + tid) * 2);
  };

  // A-piece p: convert + STS one row-block, plus rowsum into RZ column ch
  auto store_A_piece = [&](char* st, int ch, int p) {
    const int m = a_mr + p * 32;
    const float4 v = xv[p];
    const uint32_t h0 = pack_f16x2(v.x, v.y);
    const uint32_t h1 = pack_f16x2(v.z, v.w);
    const uint32_t o = sw128((uint32_t)(m * 128 + a_c4 * 8));
    *(uint2*)(st + o) = make_uint2(h0, h1);
    float rs = (v.x + v.y) + (v.z + v.w);
    rs += __shfl_xor_sync(0xffffffffu, rs, 1);
    rs += __shfl_xor_sync(0xffffffffu, rs, 2);
    rs += __shfl_xor_sync(0xffffffffu, rs, 4);
    rs += __shfl_xor_sync(0xffffffffu, rs, 8);
    if ((l & 15) == 0) {
      const __nv_bfloat16 rh = __float2bfloat16(rs);
      const __nv_bfloat16 rl = __float2bfloat16(rs - __bfloat162float(rh));
      *(__nv_bfloat16*)(smem + kRZoff        + m * 64 + ch * 2) = rh;
      *(__nv_bfloat16*)(smem + kRZoff + 8192 + m * 64 + ch * 2) = rl;
    }
  };

  auto store_B_piece = [&](char* st, int p) {
    const int kp = b_kpb + 4 * p;
    const uint32_t h_r0 = pack_f16x2((float)qva[p].x, (float)qvb[p].x);
    const uint32_t h_r1 = pack_f16x2((float)qva[p].y, (float)qvb[p].y);
    *(uint32_t*)(st + kTileB + sw128((uint32_t)(b_n0 * 128 + kp * 4)))       = h_r0;
    *(uint32_t*)(st + kTileB + sw128((uint32_t)((b_n0 + 1) * 128 + kp * 4))) = h_r1;
  };

  auto store_sz = [&](char* st, int ch) {
    if (tid < 128) {
      const float s   = szv.x;
      const float zpf = szv.y - 8.f * s;
      *(float*)(st + 2 * kTileB + tid * 4) = s;
      const __nv_bfloat16 zh = __float2bfloat16(zpf);
      const __nv_bfloat16 zl = __float2bfloat16(zpf - __bfloat162float(zh));
      *(__nv_bfloat16*)(smem + kRZoff + 16384 + tid * 64 + ch * 2) = zh;
      *(__nv_bfloat16*)(smem + kRZoff + 24576 + tid * 64 + ch * 2) = zl;
    }
  };

  // ---- prologue: stage chunk 0, preload chunk 1 ----
  load_chunk(0);
  {
    char* st0 = smem;
#pragma unroll
    for (int p = 0; p < 4; p++) store_A_piece(st0, 0, p);
#pragma unroll
    for (int p = 0; p < 4; p++) store_B_piece(st0, p);
    store_sz(st0, 0);
  }
  load_chunk(1);   // after STS of chunk 0 (WAR on staging regs)
  __syncthreads();

  // ---- main loop: one barrier per chunk; fill(ch+1) interleaved with mma(ch)
  for (int ch = 0; ch < kNCh; ch++) {
    const int buf = ch & 1;
    const uint32_t base = sbase + buf * kStageB;
    char* stn = smem + (buf ^ 1) * kStageB;      // next chunk's stage
    const bool nx = (ch + 1 < kNCh);

    float P[32];
#pragma unroll
    for (int i = 0; i < 32; i++) P[i] = 0.f;

#pragma unroll
    for (int ks = 0; ks < 4; ks++) {
      uint32_t Af[2][4], Bf[4][2];
#pragma unroll
      for (int mi = 0; mi < 2; mi++) {
        const int row = rowA0 + mi * 16;
        const uint32_t o = (uint32_t)(row * 128) +
                           (((uint32_t)(ks * 32 + segA * 16)) ^ ((row & 7) << 4));
        ldsm_x4(Af[mi], base + o);
      }
#pragma unroll
      for (int np = 0; np < 2; np++) {
        const int row = rowBx4 + np * 16;
        const uint32_t o = (uint32_t)(row * 128) +
                           (((uint32_t)(ks * 32 + segBx4 * 16)) ^ ((row & 7) << 4));
        uint32_t r[4];
        ldsm_x4(r, base + kTileB + o);
        Bf[np * 2][0]     = r[0];
        Bf[np * 2][1]     = r[1];
        Bf[np * 2 + 1][0] = r[2];
        Bf[np * 2 + 1][1] = r[3];
      }

      // interleaved fill work for chunk ch+1 / LDG for ch+2
      if (ks == 0 && nx) {
        store_A_piece(stn, ch + 1, 0);
        store_A_piece(stn, ch + 1, 1);
        store_B_piece(stn, 0);
        store_B_piece(stn, 1);
      } else if (ks == 1 && nx) {
        store_A_piece(stn, ch + 1, 2);
        store_A_piece(stn, ch + 1, 3);
        store_B_piece(stn, 2);
        store_B_piece(stn, 3);
        store_sz(stn, ch + 1);
      } else if (ks == 2 && ch + 2 < kNCh) {
        load_chunk(ch + 2);          // after all STS pieces (WAR on regs)
      }

#pragma unroll
      for (int mi = 0; mi < 2; mi++)
#pragma unroll
        for (int ni = 0; ni < 4; ni++)
          mma_f16(&P[(mi * 4 + ni) * 4], Af[mi], Bf[ni][0], Bf[ni][1]);
    }

    // rescale: mast += P * s[n]  (s of chunk ch lives in buf's stage)
    const uint32_t sb = base + 2 * kTileB;
#pragma unroll
    for (int ni = 0; ni < 4; ni++) {
      float2 sv;
      asm volatile("ld.shared.v2.f32 {%0,%1}, [%2];"
                   : "=f"(sv.x), "=f"(sv.y)
                   : "r"(sb + (uint32_t)((wn * 32 + ni * 8 + (l & 3) * 2) * 4)));
#pragma unroll
      for (int mi = 0; mi < 2; mi++) {
        float* f = &mast[(mi * 4 + ni) * 4];
        const float* p = &P[(mi * 4 + ni) * 4];
        f[0] += p[0] * sv.x;
        f[1] += p[1] * sv.y;
        f[2] += p[2] * sv.x;
        f[3] += p[3] * sv.y;
      }
    }

    __syncthreads();   // publishes stn for iter ch+1; frees buf for its refill
  }

  // ---- rank-32 zero-point correction: mast += R @ Z^T (3-term bf16 hi/lo) ----
  {
    const uint32_t Rh = sbase + kRZoff;
    const uint32_t Rl = Rh + 8192;
    const uint32_t Zh = Rh + 16384;
    const uint32_t Zl = Rh + 24576;
#pragma unroll
    for (int ks = 0; ks < 2; ks++) {
      uint32_t Arh[2][4], Arl[2][4], Bzh[4][2], Bzl[4][2];
#pragma unroll
      for (int mi = 0; mi < 2; mi++) {
        const uint32_t o = (uint32_t)((rowA0 + mi * 16) * 64 + ks * 32 + segA * 16);
        ldsm_x4(Arh[mi], Rh + o);
        ldsm_x4(Arl[mi], Rl + o);
      }
#pragma unroll
      for (int ni = 0; ni < 4; ni++) {
        const uint32_t o = (uint32_t)((rowB0 + ni * 8) * 64 + ks * 32 + segB * 16);
        ldsm_x2(Bzh[ni], Zh + o);
        ldsm_x2(Bzl[ni], Zl + o);
      }
#pragma unroll
      for (int mi = 0; mi < 2; mi++)
#pragma unroll
        for (int ni = 0; ni < 4; ni++) {
          float* c = &mast[(mi * 4 + ni) * 4];
          mma_bf16(c, Arh[mi], Bzh[ni]);
          mma_bf16(c, Arl[mi], Bzh[ni]);
          mma_bf16(c, Arh[mi], Bzl[ni]);
        }
    }
  }

  // ---- epilogue ----
#pragma unroll
  for (int mi = 0; mi < 2; mi++) {
#pragma unroll
    for (int ni = 0; ni < 4; ni++) {
      const float* c = &mast[(mi * 4 + ni) * 4];
      const int r0  = wm * 32 + mi * 16 + (l >> 2);
      const int col = n0 + wn * 32 + ni * 8 + (l & 3) * 2;
      if (r0 < nrows)
        *(float2*)(out + (size_t)(row0 + r0) * kOUT + col) = make_float2(c[0], c[1]);
      if (r0 + 8 < nrows)
        *(float2*)(out + (size_t)(row0 + r0 + 8) * kOUT + col) = make_float2(c[2], c[3]);
    }
  }
}

}  // namespace

// ---------------------------------------------------------------------------

extern "C" void kernel_launch(void* const* d_in, const int* in_sizes, int n_in,
                              void* d_out, int out_size) {
  (void)in_sizes; (void)n_in; (void)out_size;
  const float* x   = (const float*)d_in[0];
  const int*   qw  = (const int*)d_in[1];
  const float* snz = (const float*)d_in[2];
  const int*   tpe = (const int*)d_in[3];
  float* out = (float*)d_out;

  (void)cudaFuncSetAttribute(hqq_mma_kernel,
                             cudaFuncAttributeMaxDynamicSharedMemorySize, kSmemB);

  dim3 grid(kOUT / kBN, 2048 / kBM, kE);   // (16, 16, 8); empty m-tiles early-exit
  hqq_mma_kernel<<<grid, kThreads, kSmemB>>>(x, qw, snz, tpe, out);
}

// round 8
// speedup vs baseline: 1.1847x; 1.1847x over previous
#include <cuda_runtime.h>
#include <cuda_bf16.h>
#include <cuda_fp16.h>
#include <cstdint>

// ============================================================================
// HQQ grouped int4 GEMM, sm_103 base target, mma.sync fp16 path.
//
// W = q*s + zp (zp = z - 8s).  Per quant group g (K-chunk of 64):
//   P_g     = x_f16 @ q_f16     (q exact in fp16; x rounded, rel ~2^-11)
//   mast   += P_g * s[g, n]     (fp32 FFMA, s exact)
//   out    += R @ Z^T           (rank-32 zero-point correction, bf16 hi/lo)
//
// R8: CTA 256 thr, tile 64x128, 2 CTAs/SM (barrier decoupling). q staged
// byte-packed (exact: q < 16) to keep regs <= 128.
// ============================================================================

namespace {

constexpr int kE   = 8;
constexpr int kIN  = 2048;
constexpr int kOUT = 2048;
constexpr int kG   = 32;

constexpr int kBM  = 64;
constexpr int kBN  = 128;
constexpr int kBK  = 64;                  // == group size
constexpr int kNCh = kIN / kBK;           // 32
constexpr int kThreads = 256;             // 8 warps, 2x4 warp grid

constexpr int kATileB = kBM * kBK * 2;    // 8 KB
constexpr int kBTileB = kBN * kBK * 2;    // 16 KB
constexpr int kStageB = kATileB + kBTileB + 512;     // A | B | s floats = 25088
constexpr int kRZoff  = 2 * kStageB;                 // 50176
// R_hi(4K) R_lo(4K) Z_hi(8K) Z_lo(8K)
constexpr int kRhOff = kRZoff;
constexpr int kRlOff = kRZoff + 4096;
constexpr int kZhOff = kRZoff + 8192;
constexpr int kZlOff = kRZoff + 16384;
constexpr int kSmemB = kRZoff + 24576;               // 74752

// ---------------------------------------------------------------------------

__device__ __forceinline__ uint32_t smem_u32(const void* p) {
  uint32_t a;
  asm("{ .reg .u64 t; cvta.to.shared.u64 t, %1; cvt.u32.u64 %0, t; }" : "=r"(a) : "l"(p));
  return a;
}

__device__ __forceinline__ uint32_t pack_f16x2(float lo, float hi) {
  uint32_t r;
  asm("cvt.rn.f16x2.f32 %0, %1, %2;" : "=r"(r) : "f"(hi), "f"(lo));
  return r;
}

__device__ __forceinline__ uint32_t sw128(uint32_t off) {
  return off ^ ((off >> 3) & 0x70);
}

__device__ __forceinline__ void ldsm_x4(uint32_t* r, uint32_t addr) {
  asm volatile("ldmatrix.sync.aligned.m8n8.x4.shared.b16 {%0,%1,%2,%3}, [%4];"
               : "=r"(r[0]), "=r"(r[1]), "=r"(r[2]), "=r"(r[3]) : "r"(addr));
}

__device__ __forceinline__ void ldsm_x2(uint32_t* r, uint32_t addr) {
  asm volatile("ldmatrix.sync.aligned.m8n8.x2.shared.b16 {%0,%1}, [%2];"
               : "=r"(r[0]), "=r"(r[1]) : "r"(addr));
}

__device__ __forceinline__ void mma_f16(float* c, const uint32_t* a,
                                        uint32_t b0, uint32_t b1) {
  asm volatile(
      "mma.sync.aligned.m16n8k16.row.col.f32.f16.f16.f32 "
      "{%0,%1,%2,%3}, {%4,%5,%6,%7}, {%8,%9}, {%0,%1,%2,%3};"
      : "+f"(c[0]), "+f"(c[1]), "+f"(c[2]), "+f"(c[3])
      : "r"(a[0]), "r"(a[1]), "r"(a[2]), "r"(a[3]), "r"(b0), "r"(b1));
}

__device__ __forceinline__ void mma_bf16(float* c, const uint32_t* a, const uint32_t* b) {
  asm volatile(
      "mma.sync.aligned.m16n8k16.row.col.f32.bf16.bf16.f32 "
      "{%0,%1,%2,%3}, {%4,%5,%6,%7}, {%8,%9}, {%0,%1,%2,%3};"
      : "+f"(c[0]), "+f"(c[1]), "+f"(c[2]), "+f"(c[3])
      : "r"(a[0]), "r"(a[1]), "r"(a[2]), "r"(a[3]), "r"(b[0]), "r"(b[1]));
}

// bytes {a0, b0, c0, d0} (byte0 of each input, little-endian order)
__device__ __forceinline__ uint32_t pack4b(int a, int b, int c, int d) {
  return __byte_perm(__byte_perm((uint32_t)a, (uint32_t)b, 0x0040),
                     __byte_perm((uint32_t)c, (uint32_t)d, 0x0040), 0x5410);
}

// ---------------------------------------------------------------------------

__global__ void __launch_bounds__(kThreads, 2)
hqq_mma_kernel(const float* __restrict__ x,
               const int* __restrict__ qw,
               const float* __restrict__ snz,
               const int* __restrict__ tpe,
               float* __restrict__ out) {
  extern __shared__ __align__(1024) char smem[];
  const int tid = threadIdx.x;
  const int wid = tid >> 5;
  const int l   = tid & 31;

  const int e  = blockIdx.z;
  const int nt = blockIdx.x;
  const int mt = blockIdx.y;

  int off = 0, cnt = 0;
#pragma unroll
  for (int i = 0; i < kE; i++) {
    int c = __ldg(&tpe[i]);
    if (i < e) off += c;
    if (i == e) cnt = c;
  }
  if (mt * kBM >= cnt) return;

  const int row0  = off + mt * kBM;
  const int nrows = min(kBM, cnt - mt * kBM);
  const int n0    = nt * kBN;

  const uint32_t sbase = smem_u32(smem);

  // ---- fill mappings ----
  // A: 64x64, float4 col c4 = l&15, rows m = (tid>>4) + 16p, p<4
  const int a_c4 = l & 15;
  const int a_mr = tid >> 4;
  // B: pass p<8: n-pair np = (wid&3)*16 + (l>>2) + 8*(p&1);
  //              kp = (wid>>2)*16 + (l&3) + 4*(p>>1)
  const int b_npb = (wid & 3) * 16 + (l >> 2);
  const int b_kpb = (wid >> 2) * 16 + (l & 3);

  // ---- mma fragment addressing (warp grid 2x4, warp tile 32x32) ----
  const int wm = wid >> 2;                 // 0..1
  const int wn = wid & 3;                  // 0..3
  const int rowA0 = wm * 32 + (l & 15);
  const int segA  = l >> 4;
  const int rowBx4 = wn * 32 + ((l >> 4) & 1) * 8 + (l & 7);
  const int segBx4 = (l >> 3) & 1;
  const int rowB0 = wn * 32 + (l & 7);
  const int segB  = (l >> 3) & 1;

  // ---- staging ----
  float4   xv[4];
  uint32_t qpk[8];
  float2   szv = make_float2(0.f, 0.f);

  float mast[32];
#pragma unroll
  for (int i = 0; i < 32; i++) mast[i] = 0.f;

  auto load_chunk = [&](int ch) {
    const int k0 = ch * kBK;
    const float* xp = x + ((size_t)(row0 + a_mr)) * kIN + k0 + a_c4 * 4;
#pragma unroll
    for (int p = 0; p < 4; p++) {
      const int m = a_mr + p * 16;
      xv[p] = (m < nrows) ? *(const float4*)(xp + (size_t)p * 16 * kIN)
                          : make_float4(0.f, 0.f, 0.f, 0.f);
    }
#pragma unroll
    for (int p = 0; p < 8; p++) {
      const int np = b_npb + 8 * (p & 1);
      const int kk = 2 * (b_kpb + 4 * (p >> 1));
      const int* qb = qw + ((size_t)e * kIN + k0 + kk) * kOUT + n0 + 2 * np;
      const int2 a = *(const int2*)(qb);
      const int2 b = *(const int2*)(qb + kOUT);
      qpk[p] = pack4b(a.x, b.x, a.y, b.y);
    }
    if (tid < 128)
      szv = *(const float2*)(snz + (((size_t)e * kG + ch) * kOUT + n0 + tid) * 2);
  };

  auto store_chunk = [&](int buf, int ch) {
    char* st = smem + buf * kStageB;
    // A tile: fp32 -> fp16, SW128, rows 128B; rowsum -> R hi/lo
#pragma unroll
    for (int p = 0; p < 4; p++) {
      const int m = a_mr + p * 16;
      const float4 v = xv[p];
      const uint32_t h0 = pack_f16x2(v.x, v.y);
      const uint32_t h1 = pack_f16x2(v.z, v.w);
      const uint32_t o = sw128((uint32_t)(m * 128 + a_c4 * 8));
      *(uint2*)(st + o) = make_uint2(h0, h1);
      float rs = (v.x + v.y) + (v.z + v.w);
      rs += __shfl_xor_sync(0xffffffffu, rs, 1);
      rs += __shfl_xor_sync(0xffffffffu, rs, 2);
      rs += __shfl_xor_sync(0xffffffffu, rs, 4);
      rs += __shfl_xor_sync(0xffffffffu, rs, 8);
      if ((l & 15) == 0) {
        const __nv_bfloat16 rh = __float2bfloat16(rs);
        const __nv_bfloat16 rl = __float2bfloat16(rs - __bfloat162float(rh));
        *(__nv_bfloat16*)(smem + kRhOff + m * 64 + ch * 2) = rh;
        *(__nv_bfloat16*)(smem + kRlOff + m * 64 + ch * 2) = rl;
      }
    }
    // B tile: unpack bytes -> fp16 (exact), N-major rows (128B), SW128
#pragma unroll
    for (int p = 0; p < 8; p++) {
      const int np = b_npb + 8 * (p & 1);
      const int kp = b_kpb + 4 * (p >> 1);
      const uint32_t w = qpk[p];
      const uint32_t h_r0 = pack_f16x2((float)(w & 0xffu), (float)((w >> 8) & 0xffu));
      const uint32_t h_r1 = pack_f16x2((float)((w >> 16) & 0xffu), (float)(w >> 24));
      *(uint32_t*)(st + kATileB + sw128((uint32_t)((2 * np) * 128 + kp * 4)))     = h_r0;
      *(uint32_t*)(st + kATileB + sw128((uint32_t)((2 * np + 1) * 128 + kp * 4))) = h_r1;
    }
    // s array + Z (zp) hi/lo columns for this group
    if (tid < 128) {
      const float s   = szv.x;
      const float zpf = szv.y - 8.f * s;
      *(float*)(st + kATileB + kBTileB + tid * 4) = s;
      const __nv_bfloat16 zh = __float2bfloat16(zpf);
      const __nv_bfloat16 zl = __float2bfloat16(zpf - __bfloat162float(zh));
      *(__nv_bfloat16*)(smem + kZhOff + tid * 64 + ch * 2) = zh;
      *(__nv_bfloat16*)(smem + kZlOff + tid * 64 + ch * 2) = zl;
    }
  };

  // ---- main pipeline: single barrier per chunk, double-buffered ----
  load_chunk(0);
  for (int ch = 0; ch < kNCh; ch++) {
    const int buf = ch & 1;
    store_chunk(buf, ch);
    __syncthreads();
    if (ch + 1 < kNCh) load_chunk(ch + 1);

    float P[32];
#pragma unroll
    for (int i = 0; i < 32; i++) P[i] = 0.f;

    const uint32_t base = sbase + buf * kStageB;
#pragma unroll
    for (int ks = 0; ks < 4; ks++) {
      uint32_t Af[2][4], Bf[4][2];
#pragma unroll
      for (int mi = 0; mi < 2; mi++) {
        const int row = rowA0 + mi * 16;
        const uint32_t o = (uint32_t)(row * 128) +
                           (((uint32_t)(ks * 32 + segA * 16)) ^ ((row & 7) << 4));
        ldsm_x4(Af[mi], base + o);
      }
#pragma unroll
      for (int np = 0; np < 2; np++) {
        const int row = rowBx4 + np * 16;
        const uint32_t o = (uint32_t)(row * 128) +
                           (((uint32_t)(ks * 32 + segBx4 * 16)) ^ ((row & 7) << 4));
        uint32_t r[4];
        ldsm_x4(r, base + kATileB + o);
        Bf[np * 2][0]     = r[0];
        Bf[np * 2][1]     = r[1];
        Bf[np * 2 + 1][0] = r[2];
        Bf[np * 2 + 1][1] = r[3];
      }
#pragma unroll
      for (int mi = 0; mi < 2; mi++)
#pragma unroll
        for (int ni = 0; ni < 4; ni++)
          mma_f16(&P[(mi * 4 + ni) * 4], Af[mi], Bf[ni][0], Bf[ni][1]);
    }

    // rescale: mast += P * s[n]
    const uint32_t sb = base + kATileB + kBTileB;
#pragma unroll
    for (int ni = 0; ni < 4; ni++) {
      float2 sv;
      asm volatile("ld.shared.v2.f32 {%0,%1}, [%2];"
                   : "=f"(sv.x), "=f"(sv.y)
                   : "r"(sb + (uint32_t)((wn * 32 + ni * 8 + (l & 3) * 2) * 4)));
#pragma unroll
      for (int mi = 0; mi < 2; mi++) {
        float* f = &mast[(mi * 4 + ni) * 4];
        const float* p = &P[(mi * 4 + ni) * 4];
        f[0] += p[0] * sv.x;
        f[1] += p[1] * sv.y;
        f[2] += p[2] * sv.x;
        f[3] += p[3] * sv.y;
      }
    }
    // no second barrier: store(buf) at ch+2 is ordered by the barrier at ch+1
  }

  // ---- rank-32 zero-point correction: mast += R @ Z^T (3-term bf16 hi/lo) ----
  {
    const uint32_t Rh = sbase + kRhOff;
    const uint32_t Rl = sbase + kRlOff;
    const uint32_t Zh = sbase + kZhOff;
    const uint32_t Zl = sbase + kZlOff;
#pragma unroll
    for (int ks = 0; ks < 2; ks++) {
      uint32_t Arh[2][4], Arl[2][4], Bzh[4][2], Bzl[4][2];
#pragma unroll
      for (int mi = 0; mi < 2; mi++) {
        const uint32_t o = (uint32_t)((rowA0 + mi * 16) * 64 + ks * 32 + segA * 16);
        ldsm_x4(Arh[mi], Rh + o);
        ldsm_x4(Arl[mi], Rl + o);
      }
#pragma unroll
      for (int ni = 0; ni < 4; ni++) {
        const uint32_t o = (uint32_t)((rowB0 + ni * 8) * 64 + ks * 32 + segB * 16);
        ldsm_x2(Bzh[ni], Zh + o);
        ldsm_x2(Bzl[ni], Zl + o);
      }
#pragma unroll
      for (int mi = 0; mi < 2; mi++)
#pragma unroll
        for (int ni = 0; ni < 4; ni++) {
          float* c = &mast[(mi * 4 + ni) * 4];
          mma_bf16(c, Arh[mi], Bzh[ni]);
          mma_bf16(c, Arl[mi], Bzh[ni]);
          mma_bf16(c, Arh[mi], Bzl[ni]);
        }
    }
  }

  // ---- epilogue ----
#pragma unroll
  for (int mi = 0; mi < 2; mi++) {
#pragma unroll
    for (int ni = 0; ni < 4; ni++) {
      const float* c = &mast[(mi * 4 + ni) * 4];
      const int r0  = wm * 32 + mi * 16 + (l >> 2);
      const int col = n0 + wn * 32 + ni * 8 + (l & 3) * 2;
      if (r0 < nrows)
        *(float2*)(out + (size_t)(row0 + r0) * kOUT + col) = make_float2(c[0], c[1]);
      if (r0 + 8 < nrows)
        *(float2*)(out + (size_t)(row0 + r0 + 8) * kOUT + col) = make_float2(c[2], c[3]);
    }
  }
}

}  // namespace

// ---------------------------------------------------------------------------

extern "C" void kernel_launch(void* const* d_in, const int* in_sizes, int n_in,
                              void* d_out, int out_size) {
  (void)in_sizes; (void)n_in; (void)out_size;
  const float* x   = (const float*)d_in[0];
  const int*   qw  = (const int*)d_in[1];
  const float* snz = (const float*)d_in[2];
  const int*   tpe = (const int*)d_in[3];
  float* out = (float*)d_out;

  (void)cudaFuncSetAttribute(hqq_mma_kernel,
                             cudaFuncAttributeMaxDynamicSharedMemorySize, kSmemB);

  dim3 grid(kOUT / kBN, 2048 / kBM, kE);   // (16, 32, 8); empty m-tiles early-exit
  hqq_mma_kernel<<<grid, kThreads, kSmemB>>>(x, qw, snz, tpe, out);
}